// round 4
// baseline (speedup 1.0000x reference)
#include <cuda_runtime.h>

// Problem constants (fixed by the dataset)
#define B_   128
#define E_   100000
#define F_   5000
#define C_   8
#define DIN_ 10
#define DOUT_ 10
#define H_   (F_ * C_)
#define EPS_ 1e-5f
#define FPB  4   // function nodes per block (gather/scatter kernels)

// Scratch (static device mem)
__device__ float g_outT[(size_t)E_ * B_];  // outT[e][b] = x + b3; gather src & scatter dst
__device__ float g_hT[(size_t)H_ * B_];    // hT[h][b]: post-MLP hidden, batch-contiguous

// ---------------------------------------------------------------------------
// Kernel A: tiled transpose: outT[e][b] = x[b][e] + b3[e]
// ---------------------------------------------------------------------------
__global__ __launch_bounds__(256)
void transpose_init_kernel(const float* __restrict__ x,
                           const float* __restrict__ b3) {
    __shared__ float tile[32][33];
    const int e0 = blockIdx.x * 32;
    const int b0 = blockIdx.y * 32;
    const int tx = threadIdx.x, ty = threadIdx.y;

#pragma unroll
    for (int k = 0; k < 4; k++) {
        int b = b0 + ty + k * 8;
        tile[ty + k * 8][tx] = x[(size_t)b * E_ + e0 + tx];
    }
    __syncthreads();
#pragma unroll
    for (int k = 0; k < 4; k++) {
        int e = e0 + ty + k * 8;
        g_outT[(size_t)e * B_ + b0 + tx] = tile[tx][ty + k * 8] + b3[e];
    }
}

// ---------------------------------------------------------------------------
// Kernel D: tiled transpose outT[e][b] -> out[b][e]
// ---------------------------------------------------------------------------
__global__ __launch_bounds__(256)
void transpose_out_kernel(float* __restrict__ out) {
    __shared__ float tile[32][33];
    const int e0 = blockIdx.x * 32;
    const int b0 = blockIdx.y * 32;
    const int tx = threadIdx.x, ty = threadIdx.y;

#pragma unroll
    for (int k = 0; k < 4; k++) {
        int e = e0 + ty + k * 8;
        tile[ty + k * 8][tx] = g_outT[(size_t)e * B_ + b0 + tx];
    }
    __syncthreads();
#pragma unroll
    for (int k = 0; k < 4; k++) {
        int b = b0 + ty + k * 8;
        out[(size_t)b * E_ + e0 + tx] = tile[tx][ty + k * 8];
    }
}

__device__ __forceinline__ float elu1(float z) {
    return z > 0.0f ? z : expm1f(z);
}

// ---------------------------------------------------------------------------
// Kernel B: gather + MLP. 4 function nodes per block, 128 threads (=batch) each.
// Reads x as (outT - b3); writes post-elu hidden state to g_hT. NO scatter here
// (the scatter into outT races with these gathers; split gives the global barrier).
// ---------------------------------------------------------------------------
__global__ __launch_bounds__(FPB * B_)
void gather_compute_kernel(const float* __restrict__ s,
                           const float* __restrict__ w1,
                           const float* __restrict__ b1,
                           const float* __restrict__ w2,
                           const float* __restrict__ b2,
                           const float* __restrict__ b3,
                           const int*   __restrict__ src1,   // in_e[f,d] = src1[(f*10+d)*8]
                           const float* __restrict__ g1,
                           const float* __restrict__ bt1,
                           const float* __restrict__ g2,
                           const float* __restrict__ bt2) {
    __shared__ float w1s[FPB][DIN_ * C_];
    __shared__ float w2s[FPB][C_ * C_];
    __shared__ int   ine[FPB][DIN_];
    __shared__ float b3g[FPB][DIN_];
    __shared__ float b1s[FPB][C_], b2s[FPB][C_];
    __shared__ float g1s[FPB][C_], bt1s[FPB][C_], g2s[FPB][C_], bt2s[FPB][C_];

    const int tid  = threadIdx.x;
    const int floc = tid >> 7;         // 0..3
    const int lane = tid & 127;        // batch index b
    const int f    = blockIdx.x * FPB + floc;

    // ---- per-group cooperative parameter load ----
    if (lane < DIN_ * C_)  w1s[floc][lane] = w1[f * (DIN_ * C_) + lane];
    if (lane < C_ * C_)    w2s[floc][lane] = w2[f * (C_ * C_) + lane];
    if (lane < DIN_) {
        int e = src1[(f * DIN_ + lane) * C_];
        ine[floc][lane] = e;
        b3g[floc][lane] = __ldg(b3 + e);
    }
    if (lane < C_) {
        int hc = f * C_ + lane;
        b1s[floc][lane]  = b1[hc];
        b2s[floc][lane]  = b2[hc];
        g1s[floc][lane]  = g1[hc];
        bt1s[floc][lane] = bt1[hc];
        g2s[floc][lane]  = g2[hc];
        bt2s[floc][lane] = bt2[hc];
    }
    __syncthreads();

    const int b = lane;

    // ---- gather x = outT - b3 (coalesced, MLP=10) ----
    float xv[DIN_];
#pragma unroll
    for (int d = 0; d < DIN_; d++)
        xv[d] = __ldg(&g_outT[(size_t)ine[floc][d] * B_ + b]) - b3g[floc][d];

    // ---- s[b, f*8..f*8+7]: 2x LDG.128, one fully-used 32B sector per thread ----
    const float4* srow = reinterpret_cast<const float4*>(s + (size_t)b * H_ + f * C_);
    float4 sa = srow[0], sb = srow[1];
    float sv[C_] = {sa.x, sa.y, sa.z, sa.w, sb.x, sb.y, sb.z, sb.w};

    // ---- w1: 10x8 dense ----
    float h[C_];
#pragma unroll
    for (int c = 0; c < C_; c++) {
        float acc = b1s[floc][c];
#pragma unroll
        for (int d = 0; d < DIN_; d++) acc = fmaf(xv[d], w1s[floc][d * C_ + c], acc);
        h[c] = acc;
    }

    // ---- groupLN 1 + affine + elu(s*h) ----
    {
        float sum = 0.f, sq = 0.f;
#pragma unroll
        for (int c = 0; c < C_; c++) { sum += h[c]; sq += h[c] * h[c]; }
        float mu  = sum * 0.125f;
        float var = sq * 0.125f - mu * mu;
        float inv = rsqrtf(var + EPS_);
#pragma unroll
        for (int c = 0; c < C_; c++) {
            float z = (g1s[floc][c] * ((h[c] - mu) * inv) + bt1s[floc][c]) * sv[c];
            h[c] = elu1(z);
        }
    }

    // ---- w2: 8x8 dense block ----
    float h2[C_];
#pragma unroll
    for (int c2 = 0; c2 < C_; c2++) {
        float acc = b2s[floc][c2];
#pragma unroll
        for (int c = 0; c < C_; c++) acc = fmaf(h[c], w2s[floc][c * C_ + c2], acc);
        h2[c2] = acc;
    }

    // ---- groupLN 2 + affine + elu(h*s) ----
    {
        float sum = 0.f, sq = 0.f;
#pragma unroll
        for (int c = 0; c < C_; c++) { sum += h2[c]; sq += h2[c] * h2[c]; }
        float mu  = sum * 0.125f;
        float var = sq * 0.125f - mu * mu;
        float inv = rsqrtf(var + EPS_);
#pragma unroll
        for (int c = 0; c < C_; c++) {
            float z = (g2s[floc][c] * ((h2[c] - mu) * inv) + bt2s[floc][c]) * sv[c];
            h[c] = elu1(z);
        }
    }

    // ---- write hidden to scratch (coalesced, mostly L2-resident) ----
#pragma unroll
    for (int c = 0; c < C_; c++)
        g_hT[(size_t)(f * C_ + c) * B_ + b] = h[c];
}

// ---------------------------------------------------------------------------
// Kernel C: scatter. Reads hT, projects through w3 (8->10), atomics into outT.
// ---------------------------------------------------------------------------
__global__ __launch_bounds__(FPB * B_)
void scatter_kernel(const float* __restrict__ w3,
                    const int*   __restrict__ dst3) {  // out_e[f,d] = dst3[(f*10+d)*8]
    __shared__ float w3s[FPB][DOUT_ * C_];
    __shared__ int   oute[FPB][DOUT_];

    const int tid  = threadIdx.x;
    const int floc = tid >> 7;
    const int lane = tid & 127;
    const int f    = blockIdx.x * FPB + floc;

    if (lane < DOUT_ * C_) w3s[floc][lane] = w3[f * (DOUT_ * C_) + lane];
    if (lane < DOUT_)      oute[floc][lane] = dst3[(f * DOUT_ + lane) * C_];
    __syncthreads();

    const int b = lane;

    float hv[C_];
#pragma unroll
    for (int c = 0; c < C_; c++)
        hv[c] = __ldg(&g_hT[(size_t)(f * C_ + c) * B_ + b]);

#pragma unroll
    for (int d = 0; d < DOUT_; d++) {
        float acc = 0.f;
#pragma unroll
        for (int c = 0; c < C_; c++) acc = fmaf(hv[c], w3s[floc][d * C_ + c], acc);
        atomicAdd(&g_outT[(size_t)oute[floc][d] * B_ + b], acc);
    }
}

// ---------------------------------------------------------------------------
// Launch
// ---------------------------------------------------------------------------
extern "C" void kernel_launch(void* const* d_in, const int* in_sizes, int n_in,
                              void* d_out, int out_size) {
    const float* x   = (const float*)d_in[0];
    const float* s   = (const float*)d_in[1];
    const float* w1  = (const float*)d_in[2];
    const float* b1  = (const float*)d_in[3];
    const float* w2  = (const float*)d_in[4];
    const float* b2  = (const float*)d_in[5];
    const float* w3  = (const float*)d_in[6];
    const float* b3  = (const float*)d_in[7];
    const float* g1  = (const float*)d_in[8];
    const float* bt1 = (const float*)d_in[9];
    const float* g2  = (const float*)d_in[10];
    const float* bt2 = (const float*)d_in[11];
    const int*   src1 = (const int*)d_in[12];
    const int*   dst3 = (const int*)d_in[17];
    float* out = (float*)d_out;

    dim3 tblk(32, 8);
    transpose_init_kernel<<<dim3(E_ / 32, B_ / 32), tblk>>>(x, b3);
    gather_compute_kernel<<<F_ / FPB, FPB * B_>>>(s, w1, b1, w2, b2, b3,
                                                  src1, g1, bt1, g2, bt2);
    scatter_kernel<<<F_ / FPB, FPB * B_>>>(w3, dst3);
    transpose_out_kernel<<<dim3(E_ / 32, B_ / 32), tblk>>>(out);
}

// round 5
// speedup vs baseline: 1.0550x; 1.0550x over previous
#include <cuda_runtime.h>

// Problem constants (fixed by the dataset)
#define B_   128
#define E_   100000
#define F_   5000
#define C_   8
#define DIN_ 10
#define DOUT_ 10
#define H_   (F_ * C_)
#define EPS_ 1e-5f

// Transposed scratch (static device mem). Together 102.4 MB -> fits 126 MB L2.
__device__ float g_xT[(size_t)E_ * B_];    // xT[e][b]
__device__ float g_outT[(size_t)E_ * B_];  // outT[e][b] = x + b3, scatter target

// ---------------------------------------------------------------------------
// Kernel A: tiled transpose x[b][e] -> xT[e][b], and outT[e][b] = x + b3[e]
// x is single-use streaming -> __ldcs (evict-first, keep L2 for scratch).
// ---------------------------------------------------------------------------
__global__ __launch_bounds__(256)
void transpose_init_kernel(const float* __restrict__ x,
                           const float* __restrict__ b3) {
    __shared__ float tile[32][33];
    const int e0 = blockIdx.x * 32;
    const int b0 = blockIdx.y * 32;
    const int tx = threadIdx.x, ty = threadIdx.y;

#pragma unroll
    for (int k = 0; k < 4; k++) {
        int b = b0 + ty + k * 8;
        tile[ty + k * 8][tx] = __ldcs(&x[(size_t)b * E_ + e0 + tx]);
    }
    __syncthreads();
#pragma unroll
    for (int k = 0; k < 4; k++) {
        int e = e0 + ty + k * 8;
        float v = tile[tx][ty + k * 8];
        size_t idx = (size_t)e * B_ + b0 + tx;
        g_xT[idx] = v;
        g_outT[idx] = v + b3[e];
    }
}

// ---------------------------------------------------------------------------
// Kernel D: tiled transpose outT[e][b] -> out[b][e]
// out is single-use -> __stcs streaming store.
// ---------------------------------------------------------------------------
__global__ __launch_bounds__(256)
void transpose_out_kernel(float* __restrict__ out) {
    __shared__ float tile[32][33];
    const int e0 = blockIdx.x * 32;
    const int b0 = blockIdx.y * 32;
    const int tx = threadIdx.x, ty = threadIdx.y;

#pragma unroll
    for (int k = 0; k < 4; k++) {
        int e = e0 + ty + k * 8;
        tile[ty + k * 8][tx] = g_outT[(size_t)e * B_ + b0 + tx];
    }
    __syncthreads();
#pragma unroll
    for (int k = 0; k < 4; k++) {
        int b = b0 + ty + k * 8;
        __stcs(&out[(size_t)b * E_ + e0 + tx], tile[tx][ty + k * 8]);
    }
}

__device__ __forceinline__ float elu1(float z) {
    return z > 0.0f ? z : expm1f(z);
}

// ---------------------------------------------------------------------------
// Kernel C: one block per function node f, one thread per batch b (128).
// min 12 CTAs/SM to push occupancy (reg cap ~40) for gather-latency hiding.
// ---------------------------------------------------------------------------
__global__ __launch_bounds__(B_, 12)
void fn_node_kernel(const float* __restrict__ s,
                    const float* __restrict__ w1,
                    const float* __restrict__ b1,
                    const float* __restrict__ w2,
                    const float* __restrict__ b2,
                    const float* __restrict__ w3,
                    const int*   __restrict__ src1,   // in_e[f,d] = src1[(f*10+d)*8]
                    const int*   __restrict__ dst3,   // out_e[f,d] = dst3[(f*10+d)*8]
                    const float* __restrict__ g1,
                    const float* __restrict__ bt1,
                    const float* __restrict__ g2,
                    const float* __restrict__ bt2) {
    __shared__ float w1s[DIN_ * C_];
    __shared__ float w2s[C_ * C_];
    __shared__ float w3s[DOUT_ * C_];
    __shared__ int   ine[DIN_];
    __shared__ int   oute[DOUT_];
    __shared__ float b1s[C_], b2s[C_], g1s[C_], bt1s[C_], g2s[C_], bt2s[C_];

    const int f   = blockIdx.x;
    const int tid = threadIdx.x;   // == batch index b

    if (tid < DIN_ * C_)  w1s[tid] = w1[f * (DIN_ * C_) + tid];
    if (tid < C_ * C_)    w2s[tid] = w2[f * (C_ * C_) + tid];
    if (tid < DOUT_ * C_) w3s[tid] = w3[f * (DOUT_ * C_) + tid];
    if (tid < DIN_)       ine[tid]  = src1[(f * DIN_ + tid) * C_];
    if (tid < DOUT_)      oute[tid] = dst3[(f * DOUT_ + tid) * C_];
    if (tid < C_) {
        int hc = f * C_ + tid;
        b1s[tid]  = b1[hc];
        b2s[tid]  = b2[hc];
        g1s[tid]  = g1[hc];
        bt1s[tid] = bt1[hc];
        g2s[tid]  = g2[hc];
        bt2s[tid] = bt2[hc];
    }
    __syncthreads();

    const int b = tid;

    // ---- gather from transposed x: fully coalesced, MLP=10 ----
    float xv[DIN_];
#pragma unroll
    for (int d = 0; d < DIN_; d++) xv[d] = __ldg(&g_xT[(size_t)ine[d] * B_ + b]);

    // ---- s[b, f*8..f*8+7]: single-use, evict-first; one fully-used sector ----
    const float4* srow = reinterpret_cast<const float4*>(s + (size_t)b * H_ + f * C_);
    float4 sa = __ldcs(srow);
    float4 sb = __ldcs(srow + 1);
    float sv[C_] = {sa.x, sa.y, sa.z, sa.w, sb.x, sb.y, sb.z, sb.w};

    // ---- w1: 10x8 dense ----
    float h[C_];
#pragma unroll
    for (int c = 0; c < C_; c++) {
        float acc = b1s[c];
#pragma unroll
        for (int d = 0; d < DIN_; d++) acc = fmaf(xv[d], w1s[d * C_ + c], acc);
        h[c] = acc;
    }

    // ---- groupLN 1 + affine + elu(s*h) ----
    {
        float sum = 0.f, sq = 0.f;
#pragma unroll
        for (int c = 0; c < C_; c++) { sum += h[c]; sq += h[c] * h[c]; }
        float mu  = sum * 0.125f;
        float var = sq * 0.125f - mu * mu;
        float inv = rsqrtf(var + EPS_);
#pragma unroll
        for (int c = 0; c < C_; c++) {
            float z = (g1s[c] * ((h[c] - mu) * inv) + bt1s[c]) * sv[c];
            h[c] = elu1(z);
        }
    }

    // ---- w2: 8x8 dense block ----
    float h2[C_];
#pragma unroll
    for (int c2 = 0; c2 < C_; c2++) {
        float acc = b2s[c2];
#pragma unroll
        for (int c = 0; c < C_; c++) acc = fmaf(h[c], w2s[c * C_ + c2], acc);
        h2[c2] = acc;
    }

    // ---- groupLN 2 + affine + elu(h*s) ----
    {
        float sum = 0.f, sq = 0.f;
#pragma unroll
        for (int c = 0; c < C_; c++) { sum += h2[c]; sq += h2[c] * h2[c]; }
        float mu  = sum * 0.125f;
        float var = sq * 0.125f - mu * mu;
        float inv = rsqrtf(var + EPS_);
#pragma unroll
        for (int c = 0; c < C_; c++) {
            float z = (g2s[c] * ((h2[c] - mu) * inv) + bt2s[c]) * sv[c];
            h[c] = elu1(z);
        }
    }

    // ---- w3: 8 -> 10 scatter, coalesced atomics into transposed out ----
#pragma unroll
    for (int d = 0; d < DOUT_; d++) {
        float acc = 0.f;
#pragma unroll
        for (int c = 0; c < C_; c++) acc = fmaf(h[c], w3s[d * C_ + c], acc);
        atomicAdd(&g_outT[(size_t)oute[d] * B_ + b], acc);
    }
}

// ---------------------------------------------------------------------------
// Launch
// ---------------------------------------------------------------------------
extern "C" void kernel_launch(void* const* d_in, const int* in_sizes, int n_in,
                              void* d_out, int out_size) {
    const float* x   = (const float*)d_in[0];
    const float* s   = (const float*)d_in[1];
    const float* w1  = (const float*)d_in[2];
    const float* b1  = (const float*)d_in[3];
    const float* w2  = (const float*)d_in[4];
    const float* b2  = (const float*)d_in[5];
    const float* w3  = (const float*)d_in[6];
    const float* b3  = (const float*)d_in[7];
    const float* g1  = (const float*)d_in[8];
    const float* bt1 = (const float*)d_in[9];
    const float* g2  = (const float*)d_in[10];
    const float* bt2 = (const float*)d_in[11];
    const int*   src1 = (const int*)d_in[12];
    const int*   dst3 = (const int*)d_in[17];
    float* out = (float*)d_out;

    dim3 tblk(32, 8);
    transpose_init_kernel<<<dim3(E_ / 32, B_ / 32), tblk>>>(x, b3);
    fn_node_kernel<<<F_, B_>>>(s, w1, b1, w2, b2, w3,
                               src1, dst3, g1, bt1, g2, bt2);
    transpose_out_kernel<<<dim3(E_ / 32, B_ / 32), tblk>>>(out);
}

// round 6
// speedup vs baseline: 1.1333x; 1.0742x over previous
#include <cuda_runtime.h>

// Problem constants (fixed by the dataset)
#define B_   128
#define E_   100000
#define F_   5000
#define C_   8
#define DIN_ 10
#define DOUT_ 10
#define H_   (F_ * C_)
#define EPS_ 1e-5f

// Transposed scratch (static device mem)
__device__ float g_xT[(size_t)E_ * B_];    // xT[e][b]
__device__ float g_outT[(size_t)E_ * B_];  // outT[e][b] = x + b3, scatter target

// ---------------------------------------------------------------------------
// Kernel A: vectorized tiled transpose x[b][e] -> xT[e][b], outT = x + b3[e].
// Block (8,32): each thread moves one float4 per phase. Smem layout is
// transposed at store time; bank index = (4*tx + ty + i) mod 32 -> conflict-free.
// ---------------------------------------------------------------------------
__global__ __launch_bounds__(256)
void transpose_init_kernel(const float* __restrict__ x,
                           const float* __restrict__ b3) {
    __shared__ float tile[32][33];            // tile[e_loc][b_loc]
    const int e0 = blockIdx.x * 32;
    const int b0 = blockIdx.y * 32;
    const int tx = threadIdx.x;               // 0..7  (float4 index)
    const int ty = threadIdx.y;               // 0..31

    // Load: row b = b0+ty, 4 consecutive e.
    {
        const int b = b0 + ty;
        float4 v = __ldcs(reinterpret_cast<const float4*>(
                              x + (size_t)b * E_ + e0) + tx);
        tile[tx * 4 + 0][ty] = v.x;
        tile[tx * 4 + 1][ty] = v.y;
        tile[tx * 4 + 2][ty] = v.z;
        tile[tx * 4 + 3][ty] = v.w;
    }
    __syncthreads();

    // Store: row e = e0+ty, 4 consecutive b.
    {
        const int e = e0 + ty;
        float4 w;
        w.x = tile[ty][tx * 4 + 0];
        w.y = tile[ty][tx * 4 + 1];
        w.z = tile[ty][tx * 4 + 2];
        w.w = tile[ty][tx * 4 + 3];
        size_t idx = (size_t)e * B_ + b0;
        reinterpret_cast<float4*>(&g_xT[idx])[tx] = w;
        const float bias = __ldg(b3 + e);
        float4 w2;
        w2.x = w.x + bias; w2.y = w.y + bias; w2.z = w.z + bias; w2.w = w.w + bias;
        reinterpret_cast<float4*>(&g_outT[idx])[tx] = w2;
    }
}

// ---------------------------------------------------------------------------
// Kernel D: vectorized tiled transpose outT[e][b] -> out[b][e].
// ---------------------------------------------------------------------------
__global__ __launch_bounds__(256)
void transpose_out_kernel(float* __restrict__ out) {
    __shared__ float tile[32][33];            // tile[b_loc][e_loc]
    const int e0 = blockIdx.x * 32;
    const int b0 = blockIdx.y * 32;
    const int tx = threadIdx.x;               // 0..7
    const int ty = threadIdx.y;               // 0..31

    // Load: row e = e0+ty, 4 consecutive b.
    {
        const int e = e0 + ty;
        float4 v = reinterpret_cast<const float4*>(
                       &g_outT[(size_t)e * B_ + b0])[tx];
        tile[tx * 4 + 0][ty] = v.x;
        tile[tx * 4 + 1][ty] = v.y;
        tile[tx * 4 + 2][ty] = v.z;
        tile[tx * 4 + 3][ty] = v.w;
    }
    __syncthreads();

    // Store: row b = b0+ty, 4 consecutive e (streaming).
    {
        const int b = b0 + ty;
        float4 w;
        w.x = tile[ty][tx * 4 + 0];
        w.y = tile[ty][tx * 4 + 1];
        w.z = tile[ty][tx * 4 + 2];
        w.w = tile[ty][tx * 4 + 3];
        __stcs(reinterpret_cast<float4*>(out + (size_t)b * E_ + e0) + tx, w);
    }
}

__device__ __forceinline__ float elu1(float z) {
    return z > 0.0f ? z : expm1f(z);
}

// ---------------------------------------------------------------------------
// Kernel C (exact R2 config): one block per function node f, one thread per
// batch b. Natural register allocation (48), scalar coalesced atomics.
// ---------------------------------------------------------------------------
__global__ __launch_bounds__(B_)
void fn_node_kernel(const float* __restrict__ s,
                    const float* __restrict__ w1,
                    const float* __restrict__ b1,
                    const float* __restrict__ w2,
                    const float* __restrict__ b2,
                    const float* __restrict__ w3,
                    const int*   __restrict__ src1,   // in_e[f,d] = src1[(f*10+d)*8]
                    const int*   __restrict__ dst3,   // out_e[f,d] = dst3[(f*10+d)*8]
                    const float* __restrict__ g1,
                    const float* __restrict__ bt1,
                    const float* __restrict__ g2,
                    const float* __restrict__ bt2) {
    __shared__ float w1s[DIN_ * C_];
    __shared__ float w2s[C_ * C_];
    __shared__ float w3s[DOUT_ * C_];
    __shared__ int   ine[DIN_];
    __shared__ int   oute[DOUT_];
    __shared__ float b1s[C_], b2s[C_], g1s[C_], bt1s[C_], g2s[C_], bt2s[C_];

    const int f   = blockIdx.x;
    const int tid = threadIdx.x;   // == batch index b

    if (tid < DIN_ * C_)  w1s[tid] = w1[f * (DIN_ * C_) + tid];
    if (tid < C_ * C_)    w2s[tid] = w2[f * (C_ * C_) + tid];
    if (tid < DOUT_ * C_) w3s[tid] = w3[f * (DOUT_ * C_) + tid];
    if (tid < DIN_)       ine[tid]  = src1[(f * DIN_ + tid) * C_];
    if (tid < DOUT_)      oute[tid] = dst3[(f * DOUT_ + tid) * C_];
    if (tid < C_) {
        int hc = f * C_ + tid;
        b1s[tid]  = b1[hc];
        b2s[tid]  = b2[hc];
        g1s[tid]  = g1[hc];
        bt1s[tid] = bt1[hc];
        g2s[tid]  = g2[hc];
        bt2s[tid] = bt2[hc];
    }
    __syncthreads();

    const int b = tid;

    // ---- gather from transposed x: fully coalesced, MLP=10 ----
    float xv[DIN_];
#pragma unroll
    for (int d = 0; d < DIN_; d++) xv[d] = __ldg(&g_xT[(size_t)ine[d] * B_ + b]);

    // ---- s[b, f*8..f*8+7]: one fully-used 32B sector per thread ----
    const float4* srow = reinterpret_cast<const float4*>(s + (size_t)b * H_ + f * C_);
    float4 sa = srow[0], sb = srow[1];
    float sv[C_] = {sa.x, sa.y, sa.z, sa.w, sb.x, sb.y, sb.z, sb.w};

    // ---- w1: 10x8 dense ----
    float h[C_];
#pragma unroll
    for (int c = 0; c < C_; c++) {
        float acc = b1s[c];
#pragma unroll
        for (int d = 0; d < DIN_; d++) acc = fmaf(xv[d], w1s[d * C_ + c], acc);
        h[c] = acc;
    }

    // ---- groupLN 1 + affine + elu(s*h) ----
    {
        float sum = 0.f, sq = 0.f;
#pragma unroll
        for (int c = 0; c < C_; c++) { sum += h[c]; sq += h[c] * h[c]; }
        float mu  = sum * 0.125f;
        float var = sq * 0.125f - mu * mu;
        float inv = rsqrtf(var + EPS_);
#pragma unroll
        for (int c = 0; c < C_; c++) {
            float z = (g1s[c] * ((h[c] - mu) * inv) + bt1s[c]) * sv[c];
            h[c] = elu1(z);
        }
    }

    // ---- w2: 8x8 dense block ----
    float h2[C_];
#pragma unroll
    for (int c2 = 0; c2 < C_; c2++) {
        float acc = b2s[c2];
#pragma unroll
        for (int c = 0; c < C_; c++) acc = fmaf(h[c], w2s[c * C_ + c2], acc);
        h2[c2] = acc;
    }

    // ---- groupLN 2 + affine + elu(h*s) ----
    {
        float sum = 0.f, sq = 0.f;
#pragma unroll
        for (int c = 0; c < C_; c++) { sum += h2[c]; sq += h2[c] * h2[c]; }
        float mu  = sum * 0.125f;
        float var = sq * 0.125f - mu * mu;
        float inv = rsqrtf(var + EPS_);
#pragma unroll
        for (int c = 0; c < C_; c++) {
            float z = (g2s[c] * ((h2[c] - mu) * inv) + bt2s[c]) * sv[c];
            h[c] = elu1(z);
        }
    }

    // ---- w3: 8 -> 10 scatter, coalesced atomics into transposed out ----
#pragma unroll
    for (int d = 0; d < DOUT_; d++) {
        float acc = 0.f;
#pragma unroll
        for (int c = 0; c < C_; c++) acc = fmaf(h[c], w3s[d * C_ + c], acc);
        atomicAdd(&g_outT[(size_t)oute[d] * B_ + b], acc);
    }
}

// ---------------------------------------------------------------------------
// Launch
// ---------------------------------------------------------------------------
extern "C" void kernel_launch(void* const* d_in, const int* in_sizes, int n_in,
                              void* d_out, int out_size) {
    const float* x   = (const float*)d_in[0];
    const float* s   = (const float*)d_in[1];
    const float* w1  = (const float*)d_in[2];
    const float* b1  = (const float*)d_in[3];
    const float* w2  = (const float*)d_in[4];
    const float* b2  = (const float*)d_in[5];
    const float* w3  = (const float*)d_in[6];
    const float* b3  = (const float*)d_in[7];
    const float* g1  = (const float*)d_in[8];
    const float* bt1 = (const float*)d_in[9];
    const float* g2  = (const float*)d_in[10];
    const float* bt2 = (const float*)d_in[11];
    const int*   src1 = (const int*)d_in[12];
    const int*   dst3 = (const int*)d_in[17];
    float* out = (float*)d_out;

    dim3 tblk(8, 32);
    dim3 tgrid(E_ / 32, B_ / 32);
    transpose_init_kernel<<<tgrid, tblk>>>(x, b3);
    fn_node_kernel<<<F_, B_>>>(s, w1, b1, w2, b2, w3,
                               src1, dst3, g1, bt1, g2, bt2);
    transpose_out_kernel<<<tgrid, tblk>>>(out);
}